// round 9
// baseline (speedup 1.0000x reference)
#include <cuda_runtime.h>

// LightweightConv1d: x (B=8, T=4096, C=1024) fp32, weight (H=16,1,K=7) fp32.
// y[b,t,c] = sum_k softmax(w[c%H])[k] * x[b, t+k-3, c]
//
// R9: persistent-block version of the proven R3/R4 layout.
// 256 threads/block, float4 of channels per thread, GRP=8 register window.
// grid = 296 = exactly 2 blocks/SM; each block grid-strides over 2048 fine
// tiles (TCHUNK=16) -> per-block work imbalance 7-vs-6 (~1.5%) instead of the
// 2-vs-1 / 4-vs-3 block-round quantization (~6-13%) of the coarse launches.
// Halo re-reads hit L2 (proven free in R4). Softmax once per block.
// Default loads (keep input L2-resident) + evict-first stores.

#define CC   1024
#define HH   16
#define KK   7
#define PADP 3
#define TT   4096
#define BB   8
#define TCHUNK 16
#define GRP    8
#define C4   (CC / 4)           // 256 float4 lanes -> blockDim.x
#define NTILES (BB * (TT / TCHUNK))  // 2048
#define NBLOCKS 296             // 2 * 148 SMs

__global__ __launch_bounds__(C4, 2) void lightconv_kernel(
    const float* __restrict__ x,
    const float* __restrict__ weight,
    float* __restrict__ out)
{
    const int c4 = threadIdx.x;                 // 0..255

    // --- softmax of the 4 head kernels this float4 uses (once per block) ---
    const int h0 = (c4 * 4) % HH;
    float w0[KK], w1[KK], w2[KK], w3[KK];
    {
        float* wr[4] = {w0, w1, w2, w3};
        #pragma unroll
        for (int j = 0; j < 4; j++) {
            const int h = h0 + j;
            float m = -1e30f;
            #pragma unroll
            for (int k = 0; k < KK; k++) {
                wr[j][k] = weight[h * KK + k];
                m = fmaxf(m, wr[j][k]);
            }
            float s = 0.0f;
            #pragma unroll
            for (int k = 0; k < KK; k++) {
                wr[j][k] = __expf(wr[j][k] - m);
                s += wr[j][k];
            }
            const float inv = 1.0f / s;
            #pragma unroll
            for (int k = 0; k < KK; k++) wr[j][k] *= inv;
        }
    }

    const float4 z = make_float4(0.f, 0.f, 0.f, 0.f);
    const int tiles_per_b = TT / TCHUNK;        // 256

    #pragma unroll 1
    for (int tile = blockIdx.x; tile < NTILES; tile += NBLOCKS) {
        const int b  = tile / tiles_per_b;
        const int t0 = (tile % tiles_per_b) * TCHUNK;

        const float4* __restrict__ xv =
            reinterpret_cast<const float4*>(x) + (size_t)b * TT * C4 + c4;
        float4* __restrict__ ov =
            reinterpret_cast<float4*>(out) + (size_t)b * TT * C4 + c4;

        // window: v[i] holds x[base - 3 + i]
        float4 v[GRP + KK - 1];

        // prologue: v[0..5] = x[t0-3 .. t0+2]   (low guard only; t0+2 < TT)
        #pragma unroll
        for (int i = 0; i < KK - 1; i++) {
            const int t = t0 - PADP + i;
            v[i] = (t >= 0) ? xv[(size_t)t * C4] : z;
        }

        // ---- group 0: t = t0 .. t0+7 ; loads t0+3 .. t0+10 (no high guard:
        //      t0 <= 4080 -> t0+10 <= 4090 < TT) ----
        #pragma unroll
        for (int i = 0; i < GRP; i++)
            v[KK - 1 + i] = xv[(size_t)(t0 + PADP + i) * C4];

        #pragma unroll
        for (int j = 0; j < GRP; j++) {
            float4 acc = z;
            #pragma unroll
            for (int k = 0; k < KK; k++) {
                const float4 a = v[j + k];
                acc.x = fmaf(w0[k], a.x, acc.x);
                acc.y = fmaf(w1[k], a.y, acc.y);
                acc.z = fmaf(w2[k], a.z, acc.z);
                acc.w = fmaf(w3[k], a.w, acc.w);
            }
            __stcs(&ov[(size_t)(t0 + j) * C4], acc);
        }

        #pragma unroll
        for (int i = 0; i < KK - 1; i++) v[i] = v[GRP + i];

        // ---- group 1: t = t0+8 .. t0+15 ; loads t0+11 .. t0+18 (high guard) ----
        #pragma unroll
        for (int i = 0; i < GRP; i++) {
            const int t = t0 + GRP + PADP + i;
            v[KK - 1 + i] = (t < TT) ? xv[(size_t)t * C4] : z;
        }

        #pragma unroll
        for (int j = 0; j < GRP; j++) {
            float4 acc = z;
            #pragma unroll
            for (int k = 0; k < KK; k++) {
                const float4 a = v[j + k];
                acc.x = fmaf(w0[k], a.x, acc.x);
                acc.y = fmaf(w1[k], a.y, acc.y);
                acc.z = fmaf(w2[k], a.z, acc.z);
                acc.w = fmaf(w3[k], a.w, acc.w);
            }
            __stcs(&ov[(size_t)(t0 + GRP + j) * C4], acc);
        }
    }
}

extern "C" void kernel_launch(void* const* d_in, const int* in_sizes, int n_in,
                              void* d_out, int out_size)
{
    const float* x = (const float*)d_in[0];      // (B, T, C) fp32
    const float* weight = (const float*)d_in[1]; // (H, 1, K) fp32
    float* out = (float*)d_out;                  // (B, T, C) fp32

    lightconv_kernel<<<NBLOCKS, C4>>>(x, weight, out);
}